// round 14
// baseline (speedup 1.0000x reference)
#include <cuda_runtime.h>
#include <cuda_fp16.h>

// u, pregate, postgate: (4,256,128,128) f32 ; k: (256,64,64) f32
// y = postgate * irfft2( rfft2(u*pregate,256x256) * rfft2(k,256x256) )[:128,:128]

#define N_IMG   1024
#define N_CH    256
#define HH      128
#define WW      128
#define KH      64
#define KW      64
#define NF      256
#define NHF     129

// Kernel spectrum in fp16 complex (rel err ~1.4e-4, threshold 1e-3).
__device__ __half2 g_kf[(size_t)N_CH * NHF * NF];    // [c][col][k]

__device__ __forceinline__ float2 cmul(float2 a, float2 b) {
    return make_float2(a.x * b.x - a.y * b.y, a.x * b.y + a.y * b.x);
}
__device__ __forceinline__ float2 cmulc(float2 a, float wr, float wi) {
    return make_float2(a.x * wr - a.y * wi, a.x * wi + a.y * wr);
}
__device__ __forceinline__ __half2 pack_h2(float2 v) {
    return __floats2half2_rn(v.x, v.y);
}
__device__ __forceinline__ float2 unpack_h2(__half2 h) {
    return __half22float2(h);
}

#define BF1(a,b) { float ax=a.x, ay=a.y; a.x=ax+b.x; a.y=ay+b.y; b.x=ax-b.x; b.y=ay-b.y; }
#define BFI(a,b) { float ax=a.x, ay=a.y; float dx=ax-b.x, dy=ay-b.y; a.x=ax+b.x; a.y=ay+b.y; b.x=dy; b.y=-dx; }
#define BFW(a,b,wr,wi) { float ax=a.x, ay=a.y; float dx=ax-b.x, dy=ay-b.y; \
    a.x=ax+b.x; a.y=ay+b.y; b.x=dx*(wr)-dy*(wi); b.y=dx*(wi)+dy*(wr); }
#define SW(a,b) { float2 _t=a; a=b; b=_t; }
#define CADD(a,b) make_float2((a).x+(b).x, (a).y+(b).y)

#define C16_1 0.92387953251128675613f
#define S16_1 0.38268343236508977173f
#define RS2   0.70710678118654752440f

__device__ __forceinline__ void fft16_stage1(float2 r[16]) {
    BF1(r[0], r[8]);
    BFW(r[1], r[9],  C16_1, -S16_1);
    BFW(r[2], r[10], RS2,   -RS2);
    BFW(r[3], r[11], S16_1, -C16_1);
    BFI(r[4], r[12]);
    BFW(r[5], r[13], -S16_1, -C16_1);
    BFW(r[6], r[14], -RS2,   -RS2);
    BFW(r[7], r[15], -C16_1, -S16_1);
}
__device__ __forceinline__ void fft16_stage1_p8(float2 r[16]) {
    r[8]  = r[0];
    r[9]  = cmulc(r[1],  C16_1, -S16_1);
    r[10] = cmulc(r[2],  RS2,   -RS2);
    r[11] = cmulc(r[3],  S16_1, -C16_1);
    r[12] = make_float2(r[4].y, -r[4].x);
    r[13] = cmulc(r[5], -S16_1, -C16_1);
    r[14] = cmulc(r[6], -RS2,   -RS2);
    r[15] = cmulc(r[7], -C16_1, -S16_1);
}
__device__ __forceinline__ void fft16_stage12_p4(float2 r[16]) {
    r[4]  = r[0];
    r[5]  = cmulc(r[1],  RS2,   -RS2);
    r[6]  = make_float2(r[2].y, -r[2].x);
    r[7]  = cmulc(r[3], -RS2,   -RS2);
    r[8]  = r[0];
    r[9]  = cmulc(r[1],  C16_1, -S16_1);
    r[10] = cmulc(r[2],  RS2,   -RS2);
    r[11] = cmulc(r[3],  S16_1, -C16_1);
    r[12] = r[0];
    r[13] = cmulc(r[1],  S16_1, -C16_1);
    r[14] = cmulc(r[2], -RS2,   -RS2);
    r[15] = cmulc(r[3], -C16_1,  S16_1);
}
__device__ __forceinline__ void fft16_stage2(float2 r[16]) {
    BF1(r[0], r[4]);  BFW(r[1], r[5],  RS2, -RS2); BFI(r[2], r[6]);  BFW(r[3], r[7],  -RS2, -RS2);
    BF1(r[8], r[12]); BFW(r[9], r[13], RS2, -RS2); BFI(r[10],r[14]); BFW(r[11],r[15], -RS2, -RS2);
}
__device__ __forceinline__ void fft16_stage3(float2 r[16]) {
    BF1(r[0], r[2]);  BFI(r[1], r[3]);
    BF1(r[4], r[6]);  BFI(r[5], r[7]);
    BF1(r[8], r[10]); BFI(r[9], r[11]);
    BF1(r[12],r[14]); BFI(r[13],r[15]);
}
__device__ __forceinline__ void fft16_last_full(float2 r[16]) {
    BF1(r[0], r[1]);  BF1(r[2], r[3]);  BF1(r[4], r[5]);  BF1(r[6], r[7]);
    BF1(r[8], r[9]);  BF1(r[10],r[11]); BF1(r[12],r[13]); BF1(r[14],r[15]);
    SW(r[1], r[8]); SW(r[2], r[4]); SW(r[3], r[12]);
    SW(r[5], r[10]); SW(r[7], r[14]); SW(r[11], r[13]);
}
__device__ __forceinline__ void fft16_last_half(float2 r[16]) {
    float2 s0 = CADD(r[0], r[1]);
    float2 s1 = CADD(r[2], r[3]);
    float2 s2 = CADD(r[4], r[5]);
    float2 s3 = CADD(r[6], r[7]);
    float2 s4 = CADD(r[8], r[9]);
    float2 s5 = CADD(r[10],r[11]);
    float2 s6 = CADD(r[12],r[13]);
    float2 s7 = CADD(r[14],r[15]);
    r[0]=s0; r[1]=s4; r[2]=s2; r[3]=s6; r[4]=s1; r[5]=s5; r[6]=s3; r[7]=s7;
}

// 256-pt FFT, 16x16 two-pass. Tb is HALF-WARP-private, so the transpose
// syncs use the half-warp mask (0xffff << (lane&16)) instead of the full
// warp — each sync waits only on the 16 lanes that actually share Tb.
// PR: 0=dense, 1=inputs r[8..15]==0, 2=inputs r[4..15]==0.
// HALF: only outputs X[t+16*k2], k2<8.
template<int PR, bool HALF>
__device__ __forceinline__ void fft256_2pass(float2 r[16], int t, float2* Tb,
                                             const float2* twp) {
    const unsigned hmask = 0xffffu << (threadIdx.x & 16);
    if (PR == 2)      { fft16_stage12_p4(r); }
    else if (PR == 1) { fft16_stage1_p8(r); fft16_stage2(r); }
    else              { fft16_stage1(r);    fft16_stage2(r); }
    fft16_stage3(r);
    fft16_last_full(r);
    if (t) {
        const float2* twt = twp + t * 17;
#pragma unroll
        for (int k1 = 1; k1 < 16; k1++) r[k1] = cmul(r[k1], twt[k1]);
    }
    __syncwarp(hmask);                  // WAR guard vs previous use of Tb
    {
        float4* row = (float4*)(Tb + t * 18);
#pragma unroll
        for (int j = 0; j < 8; j++)
            row[j] = make_float4(r[2*j].x, r[2*j].y, r[2*j+1].x, r[2*j+1].y);
    }
    __syncwarp(hmask);                  // RAW: stores visible before loads
#pragma unroll
    for (int n2 = 0; n2 < 16; n2++) r[n2] = Tb[n2 * 18 + t];
    fft16_stage1(r);
    fft16_stage2(r);
    fft16_stage3(r);
    if (HALF) fft16_last_half(r); else fft16_last_full(r);
}

// permuted twiddle init: twp[t*17+k1] = exp(-2*pi*i*t*k1/256)
__device__ __forceinline__ void init_twp(float2* twp) {
    for (int i = threadIdx.x; i < 272; i += blockDim.x) {
        int t = i / 17, k1 = i - t * 17;
        float sn, cs;
        sincospif((float)(t * k1) / 128.0f, &sn, &cs);
        twp[i] = make_float2(cs, -sn);
    }
}

__device__ __forceinline__ float2 shfl2(float2 v, int src, unsigned mask) {
    float2 r;
    r.x = __shfl_sync(mask, v.x, src, 32);
    r.y = __shfl_sync(mask, v.y, src, 32);
    return r;
}

// ---------------------------------------------------------------------------
// Fused kernel-filter prep: one block per channel, 256 threads / 16 FFT slots.
// Smem (float2): Skf[64*129]=8256 | pool[16*288]=4608 | twp[272]
#define KF_POOL  8256
#define KF_TW    (KF_POOL + 16 * 288)
#define KF_F2    (KF_TW + 272)
#define KF_SMEM_BYTES (KF_F2 * 8)

__global__ __launch_bounds__(256)
void kf_fused_kernel(const float* __restrict__ kin) {
    extern __shared__ float2 dyn[];
    float2* Skf  = dyn;
    float2* pool = dyn + KF_POOL;
    float2* twp  = dyn + KF_TW;

    const int tid  = threadIdx.x;
    const int c    = blockIdx.x;
    const int cb   = tid >> 4;        // 0..15
    const int t    = tid & 15;
    const int lane = tid & 31;
    const int srcl = (lane & 16) | ((16 - t) & 15);
    float2* Tb = pool + cb * 288;

    init_twp(twp);
    __syncthreads();

    // Phase A: 32 packed row-pair FFTs, 2 iterations of 16
#pragma unroll 1
    for (int it = 0; it < 2; it++) {
        int p = it * 16 + cb;
        int rA = 2 * p, rB = rA + 1;
        const float* kA = kin + ((size_t)c * KH + rA) * KW;
        float2 r[16];
#pragma unroll
        for (int n1 = 0; n1 < 4; n1++) {
            int idx = 16 * n1 + t;
            r[n1] = make_float2(kA[idx], kA[KW + idx]);
        }
        fft256_2pass<2, false>(r, t, Tb, twp);
#pragma unroll
        for (int k2 = 0; k2 <= 8; k2++) {
            float2 p1 = shfl2(r[(15 - k2) & 15], srcl, 0xffffffffu);
            float2 Zm = (t == 0) ? r[(16 - k2) & 15] : p1;
            Zm.y = -Zm.y;
            float2 Z = r[k2 & 15];
            float2 A = make_float2(0.5f * (Z.x + Zm.x), 0.5f * (Z.y + Zm.y));
            float2 d = make_float2(Z.x - Zm.x, Z.y - Zm.y);
            float2 B = make_float2(0.5f * d.y, -0.5f * d.x);
            int k = t + 16 * k2;
            if (k <= 128) {
                Skf[rA * 129 + k] = A;
                Skf[rB * 129 + k] = B;
            }
        }
    }
    __syncthreads();

    // Phase B: column FFTs, 8 groups of 16 (slot 0 packs cols {0,128})
#pragma unroll 1
    for (int g = 0; g < 8; g++) {
        int cidx = g * 16 + cb;
        float2 r[16];
        if (cidx == 0) {
#pragma unroll
            for (int n1 = 0; n1 < 4; n1++) {
                int row = 16 * n1 + t;
                r[n1] = make_float2(Skf[row * 129].x, Skf[row * 129 + 128].x);
            }
        } else {
#pragma unroll
            for (int n1 = 0; n1 < 4; n1++)
                r[n1] = Skf[(16 * n1 + t) * 129 + cidx];
        }
        fft256_2pass<2, false>(r, t, Tb, twp);
        if (cidx == 0) {
            __half2* K0 = g_kf + (size_t)c * NHF * NF;
            __half2* K1 = g_kf + ((size_t)c * NHF + 128) * NF;
#pragma unroll
            for (int k2 = 0; k2 < 16; k2++) {
                float2 p1 = shfl2(r[15 - k2], srcl, 0x0000ffffu);
                float2 Zm = (t == 0) ? r[(16 - k2) & 15] : p1;
                Zm.y = -Zm.y;
                float2 Z = r[k2];
                float2 A = make_float2(0.5f * (Z.x + Zm.x), 0.5f * (Z.y + Zm.y));
                float2 d = make_float2(Z.x - Zm.x, Z.y - Zm.y);
                float2 B = make_float2(0.5f * d.y, -0.5f * d.x);
                int k = t + 16 * k2;
                K0[k] = pack_h2(A);
                K1[k] = pack_h2(B);
            }
        } else {
            __half2* dst = g_kf + ((size_t)c * NHF + cidx) * NF;
#pragma unroll
            for (int k2 = 0; k2 < 16; k2++) dst[t + 16 * k2] = pack_h2(r[k2]);
        }
    }
}

// ---------------------------------------------------------------------------
// Fused per-image kernel — exact R13 except half-warp-masked transpose syncs.
// Smem (float2): S[128*129]=16512 | pool[32*288]=9216 | twp[272]
#define SM_POOL  16512
#define SM_TW    (SM_POOL + 32 * 288)
#define SM_F2    (SM_TW + 272)
#define SMEM_BYTES (SM_F2 * 8)

__global__ __launch_bounds__(512)
void conv2d_fused_kernel(const float* __restrict__ u,
                         const float* __restrict__ pre,
                         const float* __restrict__ post,
                         float* __restrict__ out) {
    extern __shared__ float2 dyn[];
    float2* S    = dyn;
    float2* pool = dyn + SM_POOL;
    float2* twp  = dyn + SM_TW;

    const int tid  = threadIdx.x;
    // c-major remap: blocks 4c..4c+3 (same channel) run concurrently -> g_kf L2-dedup
    const int c    = blockIdx.x >> 2;
    const int b    = blockIdx.x & 3;
    const int img  = b * N_CH + c;
    const int cb   = tid >> 4;
    const int t    = tid & 15;
    const int lane = tid & 31;
    const int srcl = (lane & 16) | ((16 - t) & 15);
    const size_t ibase = (size_t)img * (HH * WW);

    init_twp(twp);
    float2* Tb = pool + cb * 288;
    __syncthreads();

    // -------- Phase 1: forward row FFTs, row pairs packed (warp-private) ---
    // (does NOT touch g_kf -> safe to run before kf_fused_kernel completes)
#pragma unroll 1
    for (int it = 0; it < 2; it++) {
        int p = it * 32 + cb;
        int rA = 2 * p, rB = rA + 1;
        const float* uA = u   + ibase + (size_t)rA * WW;
        const float* pA = pre + ibase + (size_t)rA * WW;
        float2 r[16];
#pragma unroll
        for (int n1 = 0; n1 < 8; n1++) {
            int idx = 16 * n1 + t;
            r[n1] = make_float2(uA[idx] * pA[idx],
                                uA[WW + idx] * pA[WW + idx]);
        }
        fft256_2pass<1, false>(r, t, Tb, twp);
#pragma unroll
        for (int k2 = 0; k2 <= 8; k2++) {
            float2 p1 = shfl2(r[(15 - k2) & 15], srcl, 0xffffffffu);
            float2 Zm = (t == 0) ? r[(16 - k2) & 15] : p1;
            Zm.y = -Zm.y;
            float2 Z = r[k2 & 15];
            float2 A = make_float2(0.5f * (Z.x + Zm.x), 0.5f * (Z.y + Zm.y));
            float2 d = make_float2(Z.x - Zm.x, Z.y - Zm.y);
            float2 B = make_float2(0.5f * d.y, -0.5f * d.x);
            int k = t + 16 * k2;
            if (k <= 128) {
                S[rA * 129 + k] = A;
                S[rB * 129 + k] = B;
            }
        }
    }

    // PDL: wait for kf_fused_kernel (g_kf producer) before phase 2 reads it.
    cudaGridDependencySynchronize();
    __syncthreads();

    // -------- Phase 2: column conv, next-column prefetch pipelining --------
    float2 rpre[8];
    if (cb == 0) {          // g=0 slot 0: packed pair {col 0, col 128}
#pragma unroll
        for (int n1 = 0; n1 < 8; n1++) {
            int row = 16 * n1 + t;
            rpre[n1] = make_float2(S[row * 129].x, S[row * 129 + 128].x);
        }
    } else {
#pragma unroll
        for (int n1 = 0; n1 < 8; n1++)
            rpre[n1] = S[(16 * n1 + t) * 129 + cb];
    }
#pragma unroll 1
    for (int g = 0; g < 4; g++) {
        int cidx = g * 32 + cb;
        __half2 kreg[16];
        if (cidx != 0) {      // preload filter spectrum (fp16; hides L2 latency)
            const __half2* kfc = g_kf + ((size_t)c * NHF + cidx) * NF;
#pragma unroll
            for (int k2 = 0; k2 < 16; k2++) kreg[k2] = kfc[t + 16 * k2];
        }
        float2 r[16];
#pragma unroll
        for (int n1 = 0; n1 < 8; n1++) r[n1] = rpre[n1];
        fft256_2pass<1, false>(r, t, Tb, twp);

        // prefetch next iteration's column (warp-private; untouched since
        // the phase-1 barrier) while the multiply/inverse below executes
        if (g < 3) {
            int cn = (g + 1) * 32 + cb;
#pragma unroll
            for (int n1 = 0; n1 < 8; n1++)
                rpre[n1] = S[(16 * n1 + t) * 129 + cn];
        }

        if (cidx == 0) {
            const __half2* KA = g_kf + (size_t)c * NHF * NF;
            const __half2* KB = g_kf + ((size_t)c * NHF + 128) * NF;
            float2 rn[16];
#pragma unroll
            for (int k2 = 0; k2 < 16; k2++) {
                float2 p1 = shfl2(r[15 - k2], srcl, 0x0000ffffu);
                float2 Zm = (t == 0) ? r[(16 - k2) & 15] : p1;
                Zm.y = -Zm.y;
                float2 Z = r[k2];
                float2 A = make_float2(0.5f * (Z.x + Zm.x), 0.5f * (Z.y + Zm.y));
                float2 d = make_float2(Z.x - Zm.x, Z.y - Zm.y);
                float2 B = make_float2(0.5f * d.y, -0.5f * d.x);
                int k = t + 16 * k2;
                float2 YA = cmul(A, unpack_h2(KA[k]));
                float2 YB = cmul(B, unpack_h2(KB[k]));
                rn[k2] = make_float2(YA.x - YB.y, YA.y + YB.x);
            }
#pragma unroll
            for (int k2 = 0; k2 < 16; k2++) r[k2] = rn[k2];
        } else {
#pragma unroll
            for (int k2 = 0; k2 < 16; k2++)
                r[k2] = cmul(r[k2], unpack_h2(kreg[k2]));
        }
        // inverse = conj -> fwd(half-output) -> conj
#pragma unroll
        for (int k2 = 0; k2 < 16; k2++) r[k2].y = -r[k2].y;
        fft256_2pass<0, true>(r, t, Tb, twp);
        if (cidx == 0) {
#pragma unroll
            for (int m = 0; m < 8; m++) {
                int n = t + 16 * m;
                S[n * 129]       = make_float2(r[m].x, 0.0f);
                S[n * 129 + 128] = make_float2(-r[m].y, 0.0f);
            }
        } else {
#pragma unroll
            for (int m = 0; m < 8; m++) {
                int n = t + 16 * m;
                S[n * 129 + cidx] = make_float2(r[m].x, -r[m].y);
            }
        }
    }
    __syncthreads();

    // -------- Phase 3: inverse row FFTs, row pairs packed (warp-private) ---
    const float scale = 1.0f / 65536.0f;
#pragma unroll 1
    for (int it = 0; it < 2; it++) {
        int p = it * 32 + cb;
        int rA = 2 * p, rB = rA + 1;
        float2 r[16];
#pragma unroll
        for (int n1 = 0; n1 < 16; n1++) {
            int idx = 16 * n1 + t;
            float2 YA, YB;
            if (idx <= 128) {
                YA = S[rA * 129 + idx];
                YB = S[rB * 129 + idx];
            } else {
                int m2 = 256 - idx;
                float2 a  = S[rA * 129 + m2];
                float2 b2 = S[rB * 129 + m2];
                YA = make_float2(a.x, -a.y);
                YB = make_float2(b2.x, -b2.y);
            }
            r[n1] = make_float2(YA.x - YB.y, -(YA.y + YB.x));
        }
        fft256_2pass<0, true>(r, t, Tb, twp);
        size_t oA = ibase + (size_t)rA * WW;
        size_t oB = oA + WW;
#pragma unroll
        for (int m = 0; m < 8; m++) {
            int n = t + 16 * m;
            out[oA + n] =  r[m].x * scale * post[oA + n];
            out[oB + n] = -r[m].y * scale * post[oB + n];
        }
    }
}

// ---------------------------------------------------------------------------
extern "C" void kernel_launch(void* const* d_in, const int* in_sizes, int n_in,
                              void* d_out, int out_size) {
    const float* u    = (const float*)d_in[0];
    const float* k    = (const float*)d_in[1];
    const float* pre  = (const float*)d_in[2];
    const float* post = (const float*)d_in[3];
    float* out = (float*)d_out;

    cudaFuncSetAttribute(kf_fused_kernel,
                         cudaFuncAttributeMaxDynamicSharedMemorySize, KF_SMEM_BYTES);
    cudaFuncSetAttribute(conv2d_fused_kernel,
                         cudaFuncAttributeMaxDynamicSharedMemorySize, SMEM_BYTES);

    // Primary: kernel-filter spectrum prep (fp16 g_kf)
    kf_fused_kernel<<<N_CH, 256, KF_SMEM_BYTES>>>(k);

    // Secondary: fused conv with programmatic stream serialization; phase 1
    // overlaps kf's tail, cudaGridDependencySynchronize() guards phase 2.
    cudaLaunchConfig_t cfg = {};
    cfg.gridDim = dim3(N_IMG, 1, 1);
    cfg.blockDim = dim3(512, 1, 1);
    cfg.dynamicSmemBytes = SMEM_BYTES;
    cfg.stream = 0;
    cudaLaunchAttribute attrs[1];
    attrs[0].id = cudaLaunchAttributeProgrammaticStreamSerialization;
    attrs[0].val.programmaticStreamSerializationAllowed = 1;
    cfg.attrs = attrs;
    cfg.numAttrs = 1;
    cudaLaunchKernelEx(&cfg, conv2d_fused_kernel, u, pre, post, out);
}

// round 15
// speedup vs baseline: 1.0203x; 1.0203x over previous
#include <cuda_runtime.h>
#include <cuda_fp16.h>

// u, pregate, postgate: (4,256,128,128) f32 ; k: (256,64,64) f32
// y = postgate * irfft2( rfft2(u*pregate,256x256) * rfft2(k,256x256) )[:128,:128]

#define N_IMG   1024
#define N_CH    256
#define HH      128
#define WW      128
#define KH      64
#define KW      64
#define NF      256
#define NHF     129

// Kernel spectrum in fp16 complex (rel err ~1.4e-4, threshold 1e-3).
__device__ __half2 g_kf[(size_t)N_CH * NHF * NF];    // [c][col][k]

__device__ __forceinline__ float2 cmul(float2 a, float2 b) {
    return make_float2(a.x * b.x - a.y * b.y, a.x * b.y + a.y * b.x);
}
__device__ __forceinline__ float2 cmulc(float2 a, float wr, float wi) {
    return make_float2(a.x * wr - a.y * wi, a.x * wi + a.y * wr);
}
__device__ __forceinline__ __half2 pack_h2(float2 v) {
    return __floats2half2_rn(v.x, v.y);
}
__device__ __forceinline__ float2 unpack_h2(__half2 h) {
    return __half22float2(h);
}

#define BF1(a,b) { float ax=a.x, ay=a.y; a.x=ax+b.x; a.y=ay+b.y; b.x=ax-b.x; b.y=ay-b.y; }
#define BFI(a,b) { float ax=a.x, ay=a.y; float dx=ax-b.x, dy=ay-b.y; a.x=ax+b.x; a.y=ay+b.y; b.x=dy; b.y=-dx; }
#define BFW(a,b,wr,wi) { float ax=a.x, ay=a.y; float dx=ax-b.x, dy=ay-b.y; \
    a.x=ax+b.x; a.y=ay+b.y; b.x=dx*(wr)-dy*(wi); b.y=dx*(wi)+dy*(wr); }
#define SW(a,b) { float2 _t=a; a=b; b=_t; }
#define CADD(a,b) make_float2((a).x+(b).x, (a).y+(b).y)

#define C16_1 0.92387953251128675613f
#define S16_1 0.38268343236508977173f
#define RS2   0.70710678118654752440f

__device__ __forceinline__ void fft16_stage1(float2 r[16]) {
    BF1(r[0], r[8]);
    BFW(r[1], r[9],  C16_1, -S16_1);
    BFW(r[2], r[10], RS2,   -RS2);
    BFW(r[3], r[11], S16_1, -C16_1);
    BFI(r[4], r[12]);
    BFW(r[5], r[13], -S16_1, -C16_1);
    BFW(r[6], r[14], -RS2,   -RS2);
    BFW(r[7], r[15], -C16_1, -S16_1);
}
__device__ __forceinline__ void fft16_stage1_p8(float2 r[16]) {
    r[8]  = r[0];
    r[9]  = cmulc(r[1],  C16_1, -S16_1);
    r[10] = cmulc(r[2],  RS2,   -RS2);
    r[11] = cmulc(r[3],  S16_1, -C16_1);
    r[12] = make_float2(r[4].y, -r[4].x);
    r[13] = cmulc(r[5], -S16_1, -C16_1);
    r[14] = cmulc(r[6], -RS2,   -RS2);
    r[15] = cmulc(r[7], -C16_1, -S16_1);
}
__device__ __forceinline__ void fft16_stage12_p4(float2 r[16]) {
    r[4]  = r[0];
    r[5]  = cmulc(r[1],  RS2,   -RS2);
    r[6]  = make_float2(r[2].y, -r[2].x);
    r[7]  = cmulc(r[3], -RS2,   -RS2);
    r[8]  = r[0];
    r[9]  = cmulc(r[1],  C16_1, -S16_1);
    r[10] = cmulc(r[2],  RS2,   -RS2);
    r[11] = cmulc(r[3],  S16_1, -C16_1);
    r[12] = r[0];
    r[13] = cmulc(r[1],  S16_1, -C16_1);
    r[14] = cmulc(r[2], -RS2,   -RS2);
    r[15] = cmulc(r[3], -C16_1,  S16_1);
}
__device__ __forceinline__ void fft16_stage2(float2 r[16]) {
    BF1(r[0], r[4]);  BFW(r[1], r[5],  RS2, -RS2); BFI(r[2], r[6]);  BFW(r[3], r[7],  -RS2, -RS2);
    BF1(r[8], r[12]); BFW(r[9], r[13], RS2, -RS2); BFI(r[10],r[14]); BFW(r[11],r[15], -RS2, -RS2);
}
__device__ __forceinline__ void fft16_stage3(float2 r[16]) {
    BF1(r[0], r[2]);  BFI(r[1], r[3]);
    BF1(r[4], r[6]);  BFI(r[5], r[7]);
    BF1(r[8], r[10]); BFI(r[9], r[11]);
    BF1(r[12],r[14]); BFI(r[13],r[15]);
}
__device__ __forceinline__ void fft16_last_full(float2 r[16]) {
    BF1(r[0], r[1]);  BF1(r[2], r[3]);  BF1(r[4], r[5]);  BF1(r[6], r[7]);
    BF1(r[8], r[9]);  BF1(r[10],r[11]); BF1(r[12],r[13]); BF1(r[14],r[15]);
    SW(r[1], r[8]); SW(r[2], r[4]); SW(r[3], r[12]);
    SW(r[5], r[10]); SW(r[7], r[14]); SW(r[11], r[13]);
}
__device__ __forceinline__ void fft16_last_half(float2 r[16]) {
    float2 s0 = CADD(r[0], r[1]);
    float2 s1 = CADD(r[2], r[3]);
    float2 s2 = CADD(r[4], r[5]);
    float2 s3 = CADD(r[6], r[7]);
    float2 s4 = CADD(r[8], r[9]);
    float2 s5 = CADD(r[10],r[11]);
    float2 s6 = CADD(r[12],r[13]);
    float2 s7 = CADD(r[14],r[15]);
    r[0]=s0; r[1]=s4; r[2]=s2; r[3]=s6; r[4]=s1; r[5]=s5; r[6]=s3; r[7]=s7;
}

// 256-pt FFT, 16x16 two-pass, warp-local sync only (round-6 proven config).
// PR: 0=dense, 1=inputs r[8..15]==0, 2=inputs r[4..15]==0.
// HALF: only outputs X[t+16*k2], k2<8.
template<int PR, bool HALF>
__device__ __forceinline__ void fft256_2pass(float2 r[16], int t, float2* Tb,
                                             const float2* twp) {
    if (PR == 2)      { fft16_stage12_p4(r); }
    else if (PR == 1) { fft16_stage1_p8(r); fft16_stage2(r); }
    else              { fft16_stage1(r);    fft16_stage2(r); }
    fft16_stage3(r);
    fft16_last_full(r);
    if (t) {
        const float2* twt = twp + t * 17;
#pragma unroll
        for (int k1 = 1; k1 < 16; k1++) r[k1] = cmul(r[k1], twt[k1]);
    }
    __syncwarp();
    {
        float4* row = (float4*)(Tb + t * 18);
#pragma unroll
        for (int j = 0; j < 8; j++)
            row[j] = make_float4(r[2*j].x, r[2*j].y, r[2*j+1].x, r[2*j+1].y);
    }
    __syncwarp();
#pragma unroll
    for (int n2 = 0; n2 < 16; n2++) r[n2] = Tb[n2 * 18 + t];
    fft16_stage1(r);
    fft16_stage2(r);
    fft16_stage3(r);
    if (HALF) fft16_last_half(r); else fft16_last_full(r);
}

// permuted twiddle init: twp[t*17+k1] = exp(-2*pi*i*t*k1/256)
__device__ __forceinline__ void init_twp(float2* twp) {
    for (int i = threadIdx.x; i < 272; i += blockDim.x) {
        int t = i / 17, k1 = i - t * 17;
        float sn, cs;
        sincospif((float)(t * k1) / 128.0f, &sn, &cs);
        twp[i] = make_float2(cs, -sn);
    }
}

__device__ __forceinline__ float2 shfl2(float2 v, int src, unsigned mask) {
    float2 r;
    r.x = __shfl_sync(mask, v.x, src, 32);
    r.y = __shfl_sync(mask, v.y, src, 32);
    return r;
}

// ---------------------------------------------------------------------------
// Fused kernel-filter prep: one block per channel, 256 threads / 16 FFT slots.
// Smem (float2): Skf[64*129]=8256 | pool[16*288]=4608 | twp[272]
#define KF_POOL  8256
#define KF_TW    (KF_POOL + 16 * 288)
#define KF_F2    (KF_TW + 272)
#define KF_SMEM_BYTES (KF_F2 * 8)

__global__ __launch_bounds__(256)
void kf_fused_kernel(const float* __restrict__ kin) {
    extern __shared__ float2 dyn[];
    float2* Skf  = dyn;
    float2* pool = dyn + KF_POOL;
    float2* twp  = dyn + KF_TW;

    const int tid  = threadIdx.x;
    const int c    = blockIdx.x;
    const int cb   = tid >> 4;        // 0..15
    const int t    = tid & 15;
    const int lane = tid & 31;
    const int srcl = (lane & 16) | ((16 - t) & 15);
    float2* Tb = pool + cb * 288;

    init_twp(twp);
    __syncthreads();

    // Phase A: 32 packed row-pair FFTs, 2 iterations of 16
#pragma unroll 1
    for (int it = 0; it < 2; it++) {
        int p = it * 16 + cb;
        int rA = 2 * p, rB = rA + 1;
        const float* kA = kin + ((size_t)c * KH + rA) * KW;
        float2 r[16];
#pragma unroll
        for (int n1 = 0; n1 < 4; n1++) {
            int idx = 16 * n1 + t;
            r[n1] = make_float2(kA[idx], kA[KW + idx]);
        }
        fft256_2pass<2, false>(r, t, Tb, twp);
#pragma unroll
        for (int k2 = 0; k2 <= 8; k2++) {
            float2 p1 = shfl2(r[(15 - k2) & 15], srcl, 0xffffffffu);
            float2 Zm = (t == 0) ? r[(16 - k2) & 15] : p1;
            Zm.y = -Zm.y;
            float2 Z = r[k2 & 15];
            float2 A = make_float2(0.5f * (Z.x + Zm.x), 0.5f * (Z.y + Zm.y));
            float2 d = make_float2(Z.x - Zm.x, Z.y - Zm.y);
            float2 B = make_float2(0.5f * d.y, -0.5f * d.x);
            int k = t + 16 * k2;
            if (k <= 128) {
                Skf[rA * 129 + k] = A;
                Skf[rB * 129 + k] = B;
            }
        }
    }
    __syncthreads();

    // Phase B: column FFTs, 8 groups of 16 (slot 0 packs cols {0,128})
#pragma unroll 1
    for (int g = 0; g < 8; g++) {
        int cidx = g * 16 + cb;
        float2 r[16];
        if (cidx == 0) {
#pragma unroll
            for (int n1 = 0; n1 < 4; n1++) {
                int row = 16 * n1 + t;
                r[n1] = make_float2(Skf[row * 129].x, Skf[row * 129 + 128].x);
            }
        } else {
#pragma unroll
            for (int n1 = 0; n1 < 4; n1++)
                r[n1] = Skf[(16 * n1 + t) * 129 + cidx];
        }
        fft256_2pass<2, false>(r, t, Tb, twp);
        if (cidx == 0) {
            __half2* K0 = g_kf + (size_t)c * NHF * NF;
            __half2* K1 = g_kf + ((size_t)c * NHF + 128) * NF;
#pragma unroll
            for (int k2 = 0; k2 < 16; k2++) {
                float2 p1 = shfl2(r[15 - k2], srcl, 0x0000ffffu);
                float2 Zm = (t == 0) ? r[(16 - k2) & 15] : p1;
                Zm.y = -Zm.y;
                float2 Z = r[k2];
                float2 A = make_float2(0.5f * (Z.x + Zm.x), 0.5f * (Z.y + Zm.y));
                float2 d = make_float2(Z.x - Zm.x, Z.y - Zm.y);
                float2 B = make_float2(0.5f * d.y, -0.5f * d.x);
                int k = t + 16 * k2;
                K0[k] = pack_h2(A);
                K1[k] = pack_h2(B);
            }
        } else {
            __half2* dst = g_kf + ((size_t)c * NHF + cidx) * NF;
#pragma unroll
            for (int k2 = 0; k2 < 16; k2++) dst[t + 16 * k2] = pack_h2(r[k2]);
        }
    }
}

// ---------------------------------------------------------------------------
// Fused per-image kernel — best measured config (R13): R6 FFT shape,
// fp16 g_kf, PDL launch, phase-2 next-column prefetch.
// Smem (float2): S[128*129]=16512 | pool[32*288]=9216 | twp[272]
#define SM_POOL  16512
#define SM_TW    (SM_POOL + 32 * 288)
#define SM_F2    (SM_TW + 272)
#define SMEM_BYTES (SM_F2 * 8)

__global__ __launch_bounds__(512)
void conv2d_fused_kernel(const float* __restrict__ u,
                         const float* __restrict__ pre,
                         const float* __restrict__ post,
                         float* __restrict__ out) {
    extern __shared__ float2 dyn[];
    float2* S    = dyn;
    float2* pool = dyn + SM_POOL;
    float2* twp  = dyn + SM_TW;

    const int tid  = threadIdx.x;
    // c-major remap: blocks 4c..4c+3 (same channel) run concurrently -> g_kf L2-dedup
    const int c    = blockIdx.x >> 2;
    const int b    = blockIdx.x & 3;
    const int img  = b * N_CH + c;
    const int cb   = tid >> 4;
    const int t    = tid & 15;
    const int lane = tid & 31;
    const int srcl = (lane & 16) | ((16 - t) & 15);
    const size_t ibase = (size_t)img * (HH * WW);

    init_twp(twp);
    float2* Tb = pool + cb * 288;
    __syncthreads();

    // -------- Phase 1: forward row FFTs, row pairs packed (warp-private) ---
    // (does NOT touch g_kf -> safe to run before kf_fused_kernel completes)
#pragma unroll 1
    for (int it = 0; it < 2; it++) {
        int p = it * 32 + cb;
        int rA = 2 * p, rB = rA + 1;
        const float* uA = u   + ibase + (size_t)rA * WW;
        const float* pA = pre + ibase + (size_t)rA * WW;
        float2 r[16];
#pragma unroll
        for (int n1 = 0; n1 < 8; n1++) {
            int idx = 16 * n1 + t;
            r[n1] = make_float2(uA[idx] * pA[idx],
                                uA[WW + idx] * pA[WW + idx]);
        }
        fft256_2pass<1, false>(r, t, Tb, twp);
#pragma unroll
        for (int k2 = 0; k2 <= 8; k2++) {
            float2 p1 = shfl2(r[(15 - k2) & 15], srcl, 0xffffffffu);
            float2 Zm = (t == 0) ? r[(16 - k2) & 15] : p1;
            Zm.y = -Zm.y;
            float2 Z = r[k2 & 15];
            float2 A = make_float2(0.5f * (Z.x + Zm.x), 0.5f * (Z.y + Zm.y));
            float2 d = make_float2(Z.x - Zm.x, Z.y - Zm.y);
            float2 B = make_float2(0.5f * d.y, -0.5f * d.x);
            int k = t + 16 * k2;
            if (k <= 128) {
                S[rA * 129 + k] = A;
                S[rB * 129 + k] = B;
            }
        }
    }

    // PDL: wait for kf_fused_kernel (g_kf producer) before phase 2 reads it.
    cudaGridDependencySynchronize();
    __syncthreads();

    // -------- Phase 2: column conv, next-column prefetch pipelining --------
    float2 rpre[8];
    if (cb == 0) {          // g=0 slot 0: packed pair {col 0, col 128}
#pragma unroll
        for (int n1 = 0; n1 < 8; n1++) {
            int row = 16 * n1 + t;
            rpre[n1] = make_float2(S[row * 129].x, S[row * 129 + 128].x);
        }
    } else {
#pragma unroll
        for (int n1 = 0; n1 < 8; n1++)
            rpre[n1] = S[(16 * n1 + t) * 129 + cb];
    }
#pragma unroll 1
    for (int g = 0; g < 4; g++) {
        int cidx = g * 32 + cb;
        __half2 kreg[16];
        if (cidx != 0) {      // preload filter spectrum (fp16; hides L2 latency)
            const __half2* kfc = g_kf + ((size_t)c * NHF + cidx) * NF;
#pragma unroll
            for (int k2 = 0; k2 < 16; k2++) kreg[k2] = kfc[t + 16 * k2];
        }
        float2 r[16];
#pragma unroll
        for (int n1 = 0; n1 < 8; n1++) r[n1] = rpre[n1];
        fft256_2pass<1, false>(r, t, Tb, twp);

        // prefetch next iteration's column (warp-private; untouched since
        // the phase-1 barrier) while the multiply/inverse below executes
        if (g < 3) {
            int cn = (g + 1) * 32 + cb;
#pragma unroll
            for (int n1 = 0; n1 < 8; n1++)
                rpre[n1] = S[(16 * n1 + t) * 129 + cn];
        }

        if (cidx == 0) {
            const __half2* KA = g_kf + (size_t)c * NHF * NF;
            const __half2* KB = g_kf + ((size_t)c * NHF + 128) * NF;
            float2 rn[16];
#pragma unroll
            for (int k2 = 0; k2 < 16; k2++) {
                float2 p1 = shfl2(r[15 - k2], srcl, 0x0000ffffu);
                float2 Zm = (t == 0) ? r[(16 - k2) & 15] : p1;
                Zm.y = -Zm.y;
                float2 Z = r[k2];
                float2 A = make_float2(0.5f * (Z.x + Zm.x), 0.5f * (Z.y + Zm.y));
                float2 d = make_float2(Z.x - Zm.x, Z.y - Zm.y);
                float2 B = make_float2(0.5f * d.y, -0.5f * d.x);
                int k = t + 16 * k2;
                float2 YA = cmul(A, unpack_h2(KA[k]));
                float2 YB = cmul(B, unpack_h2(KB[k]));
                rn[k2] = make_float2(YA.x - YB.y, YA.y + YB.x);
            }
#pragma unroll
            for (int k2 = 0; k2 < 16; k2++) r[k2] = rn[k2];
        } else {
#pragma unroll
            for (int k2 = 0; k2 < 16; k2++)
                r[k2] = cmul(r[k2], unpack_h2(kreg[k2]));
        }
        // inverse = conj -> fwd(half-output) -> conj
#pragma unroll
        for (int k2 = 0; k2 < 16; k2++) r[k2].y = -r[k2].y;
        fft256_2pass<0, true>(r, t, Tb, twp);
        if (cidx == 0) {
#pragma unroll
            for (int m = 0; m < 8; m++) {
                int n = t + 16 * m;
                S[n * 129]       = make_float2(r[m].x, 0.0f);
                S[n * 129 + 128] = make_float2(-r[m].y, 0.0f);
            }
        } else {
#pragma unroll
            for (int m = 0; m < 8; m++) {
                int n = t + 16 * m;
                S[n * 129 + cidx] = make_float2(r[m].x, -r[m].y);
            }
        }
    }
    __syncthreads();

    // -------- Phase 3: inverse row FFTs, row pairs packed (warp-private) ---
    const float scale = 1.0f / 65536.0f;
#pragma unroll 1
    for (int it = 0; it < 2; it++) {
        int p = it * 32 + cb;
        int rA = 2 * p, rB = rA + 1;
        float2 r[16];
#pragma unroll
        for (int n1 = 0; n1 < 16; n1++) {
            int idx = 16 * n1 + t;
            float2 YA, YB;
            if (idx <= 128) {
                YA = S[rA * 129 + idx];
                YB = S[rB * 129 + idx];
            } else {
                int m2 = 256 - idx;
                float2 a  = S[rA * 129 + m2];
                float2 b2 = S[rB * 129 + m2];
                YA = make_float2(a.x, -a.y);
                YB = make_float2(b2.x, -b2.y);
            }
            r[n1] = make_float2(YA.x - YB.y, -(YA.y + YB.x));
        }
        fft256_2pass<0, true>(r, t, Tb, twp);
        size_t oA = ibase + (size_t)rA * WW;
        size_t oB = oA + WW;
#pragma unroll
        for (int m = 0; m < 8; m++) {
            int n = t + 16 * m;
            out[oA + n] =  r[m].x * scale * post[oA + n];
            out[oB + n] = -r[m].y * scale * post[oB + n];
        }
    }
}

// ---------------------------------------------------------------------------
extern "C" void kernel_launch(void* const* d_in, const int* in_sizes, int n_in,
                              void* d_out, int out_size) {
    const float* u    = (const float*)d_in[0];
    const float* k    = (const float*)d_in[1];
    const float* pre  = (const float*)d_in[2];
    const float* post = (const float*)d_in[3];
    float* out = (float*)d_out;

    cudaFuncSetAttribute(kf_fused_kernel,
                         cudaFuncAttributeMaxDynamicSharedMemorySize, KF_SMEM_BYTES);
    cudaFuncSetAttribute(conv2d_fused_kernel,
                         cudaFuncAttributeMaxDynamicSharedMemorySize, SMEM_BYTES);

    // Primary: kernel-filter spectrum prep (fp16 g_kf)
    kf_fused_kernel<<<N_CH, 256, KF_SMEM_BYTES>>>(k);

    // Secondary: fused conv with programmatic stream serialization; phase 1
    // overlaps kf's tail, cudaGridDependencySynchronize() guards phase 2.
    cudaLaunchConfig_t cfg = {};
    cfg.gridDim = dim3(N_IMG, 1, 1);
    cfg.blockDim = dim3(512, 1, 1);
    cfg.dynamicSmemBytes = SMEM_BYTES;
    cfg.stream = 0;
    cudaLaunchAttribute attrs[1];
    attrs[0].id = cudaLaunchAttributeProgrammaticStreamSerialization;
    attrs[0].val.programmaticStreamSerializationAllowed = 1;
    cfg.attrs = attrs;
    cfg.numAttrs = 1;
    cudaLaunchKernelEx(&cfg, conv2d_fused_kernel, u, pre, post, out);
}